// round 14
// baseline (speedup 1.0000x reference)
#include <cuda_runtime.h>
#include <cuda_fp16.h>
#include <math.h>
#include <stdint.h>

#define N_NODES 10000
#define N_EDGES 640000
#define D_IN    256
#define D_H1    64
#define D_H2    32
#define D_OUT   16

#define K_PAD   10016            // 313 * 32
#define M_PAD   10112            // 79 * 128
#define KT      313

// ---------------- scratch (device globals; no allocation allowed) ------------
__device__ __half g_Bh[(size_t)K_PAD * D_IN];    // fp16 emb, K-padded
__device__ float g_h [N_NODES * D_IN];
__device__ float g_t1[N_NODES * D_H1];
__device__ float g_a1[N_NODES * D_H1];
__device__ float g_t2[N_NODES * D_H2];
__device__ float g_a2[N_NODES * D_H2];
__device__ int   g_src[N_EDGES];
__device__ int   g_dst[N_EDGES];
__device__ int   g_csr_src[N_EDGES];
__device__ float g_csr_w[N_EDGES];
__device__ int   g_rowptr[N_NODES + 1];
__device__ int   g_cursor[N_NODES];
__device__ int   g_deg [N_NODES];
__device__ float g_dinv[N_NODES];
__device__ int   g_is64;

// ---------------- edge index dtype detection + decode (+deg count) -----------
__global__ void k_detect(const void* __restrict__ ei) {
    if (threadIdx.x == 0 && blockIdx.x == 0) {
        const long long* p = (const long long*)ei;
        int ok = 1;
        for (int i = 0; i < 16; i++) {
            long long v = p[i];
            if (v < 0 || v >= N_NODES) ok = 0;
        }
        g_is64 = ok;
    }
}

__global__ void k_decode_deg(const void* __restrict__ ei) {
    int e = blockIdx.x * blockDim.x + threadIdx.x;
    if (e >= N_EDGES) return;
    int s, d;
    if (g_is64) {
        const long long* p = (const long long*)ei;
        s = (int)p[e]; d = (int)p[N_EDGES + e];
    } else {
        const int* p = (const int*)ei;
        s = p[e]; d = p[N_EDGES + e];
    }
    g_src[e] = s;
    g_dst[e] = d;
    atomicAdd(&g_deg[d], 1);
}

// ---------------- CSR build: shfl scan + dinv ---------------------------------
__global__ __launch_bounds__(1024) void k_scan() {     // single block
    __shared__ int wsum[32];
    const int t    = threadIdx.x;
    const int lane = t & 31;
    const int wrp  = t >> 5;
    const int base = t * 10;
    int loc[10];
    int s = 0;
#pragma unroll
    for (int j = 0; j < 10; j++) {
        int i = base + j;
        int v = (i < N_NODES) ? g_deg[i] : 0;
        loc[j] = s;
        s += v;
        if (i < N_NODES) g_dinv[i] = rsqrtf((float)(v + 1));
    }
    // warp inclusive scan of s
    int inc = s;
#pragma unroll
    for (int off = 1; off < 32; off <<= 1) {
        int v = __shfl_up_sync(0xffffffffu, inc, off);
        if (lane >= off) inc += v;
    }
    if (lane == 31) wsum[wrp] = inc;
    __syncthreads();
    if (wrp == 0) {
        int v = wsum[lane];
        int wi = v;
#pragma unroll
        for (int off = 1; off < 32; off <<= 1) {
            int u = __shfl_up_sync(0xffffffffu, wi, off);
            if (lane >= off) wi += u;
        }
        wsum[lane] = wi - v;     // exclusive warp prefix
    }
    __syncthreads();
    int pre = wsum[wrp] + inc - s;   // exclusive prefix for this thread
#pragma unroll
    for (int j = 0; j < 10; j++) {
        int i = base + j;
        if (i < N_NODES) {
            g_rowptr[i] = pre + loc[j];
            g_cursor[i] = pre + loc[j];
        }
    }
    if (t == 1023) g_rowptr[N_NODES] = pre + s;
}

__global__ void k_fill_csr() {
    int e = blockIdx.x * blockDim.x + threadIdx.x;
    if (e >= N_EDGES) return;
    int s = g_src[e], d = g_dst[e];
    int pos = atomicAdd(&g_cursor[d], 1);
    g_csr_src[pos] = s;
    g_csr_w[pos]   = g_dinv[s];
}

// ---------------- fp16 prep for B (emb) ---------------------------------------
__global__ void k_prep_b(const float* __restrict__ emb) {
    int chunk = blockIdx.x * blockDim.x + threadIdx.x; // 8-half chunk
    if (chunk >= K_PAD * D_IN / 8) return;
    int row = chunk >> 5;
    int c   = chunk & 31;
    __half2 h[4];
    if (row < N_NODES) {
        const float4* p = (const float4*)&emb[(size_t)row * D_IN + c * 8];
        float4 v0 = p[0], v1 = p[1];
        h[0] = __floats2half2_rn(v0.x, v0.y);
        h[1] = __floats2half2_rn(v0.z, v0.w);
        h[2] = __floats2half2_rn(v1.x, v1.y);
        h[3] = __floats2half2_rn(v1.z, v1.w);
    } else {
        h[0] = h[1] = h[2] = h[3] = __floats2half2_rn(0.f, 0.f);
    }
    *(uint4*)&g_Bh[(size_t)row * D_IN + c * 8] = *(uint4*)h;
}

// ---------------- GEMM1 (fp16 HMMA, fp32 A staged + inline convert) -----------
// BM=128 BN=256 BK=32, 512 threads (16 warps = 4M x 4N), 4 smem stages.
// A staged as fp32 (cp.async, zero-fill tails); fragments built by LDS.64+cvt.
#define LDA_F 40                       // fp32 A stage stride (floats) — conflict-free
#define LDB_H 264
#define ASTG_F (128 * LDA_F)           // 5120 floats = 20480 B per stage
#define BSTG_H (32 * LDB_H)            // 8448 halfs  = 16896 B per stage
#define B_BYTE_OFF (4 * ASTG_F * 4)    // 81920
#define GEMM_SMEM (4 * ASTG_F * 4 + 4 * BSTG_H * 2)   // 149504 B

__device__ __forceinline__ uint32_t smem_u32(const void* p) {
    uint32_t a;
    asm("{ .reg .u64 t; cvta.to.shared.u64 t, %1; cvt.u32.u64 %0, t; }"
        : "=r"(a) : "l"(p));
    return a;
}
__device__ __forceinline__ void cp16(uint32_t dst, const void* src) {
    asm volatile("cp.async.cg.shared.global [%0], [%1], 16;" :: "r"(dst), "l"(src) : "memory");
}
__device__ __forceinline__ void cp16p(uint32_t dst, const void* src, bool valid) {
    int sz = valid ? 16 : 0;
    asm volatile("cp.async.cg.shared.global [%0], [%1], 16, %2;"
                 :: "r"(dst), "l"(src), "r"(sz) : "memory");
}
__device__ __forceinline__ void cp_commit() {
    asm volatile("cp.async.commit_group;" ::: "memory");
}
template <int NW>
__device__ __forceinline__ void cp_wait() {
    asm volatile("cp.async.wait_group %0;" :: "n"(NW) : "memory");
}
__device__ __forceinline__ void ldsm4t(uint32_t* r, uint32_t addr) {
    asm volatile("ldmatrix.sync.aligned.m8n8.x4.trans.shared.b16 {%0,%1,%2,%3}, [%4];"
                 : "=r"(r[0]), "=r"(r[1]), "=r"(r[2]), "=r"(r[3]) : "r"(addr));
}
__device__ __forceinline__ void mma_f16(float* c, const uint32_t* a, uint32_t b0, uint32_t b1) {
    asm volatile(
        "mma.sync.aligned.m16n8k16.row.col.f32.f16.f16.f32 "
        "{%0,%1,%2,%3}, {%4,%5,%6,%7}, {%8,%9}, {%0,%1,%2,%3};"
        : "+f"(c[0]), "+f"(c[1]), "+f"(c[2]), "+f"(c[3])
        : "r"(a[0]), "r"(a[1]), "r"(a[2]), "r"(a[3]), "r"(b0), "r"(b1));
}
__device__ __forceinline__ uint32_t packh2(float lo, float hi) {
    uint32_t r;
    asm("cvt.rn.f16x2.f32 %0, %1, %2;" : "=r"(r) : "f"(hi), "f"(lo));
    return r;
}

__global__ __launch_bounds__(512, 1)
void k_gemm1_f16(const float* __restrict__ X)   // x [10000,10000] fp32
{
    extern __shared__ float smf[];

    const int tid  = threadIdx.x;
    const int lane = tid & 31;
    const int wid  = tid >> 5;
    const int wm   = wid & 3;        // 0..3 (M)
    const int wn   = wid >> 2;       // 0..3 (N)
    const int m0   = blockIdx.x * 128;
    const uint32_t sbase = smem_u32(smf);

    float acc[2][8][4];
#pragma unroll
    for (int mi = 0; mi < 2; mi++)
#pragma unroll
        for (int ni = 0; ni < 8; ni++)
#pragma unroll
            for (int r = 0; r < 4; r++) acc[mi][ni][r] = 0.0f;

    // fill: A 1024 fp32 chunks (2/thread), B 1024 fp16 chunks (2/thread)
    auto fill = [&](int slot, int it) {
        const int k0 = it * 32;
#pragma unroll
        for (int i = 0; i < 2; i++) {
            int ch  = tid + i * 512;
            int row = ch >> 3, c4 = ch & 7;          // 8 chunks per 32-float row
            int gm  = m0 + row;
            int gk  = k0 + c4 * 4;
            bool v  = (gm < N_NODES) && (gk < N_NODES);
            const float* src = v ? &X[(size_t)gm * N_NODES + gk] : X;
            cp16p(sbase + (slot * ASTG_F + row * LDA_F + c4 * 4) * 4, src, v);
        }
#pragma unroll
        for (int i = 0; i < 2; i++) {
            int ch  = tid + i * 512;
            int row = ch >> 5, c = ch & 31;          // 32 chunks per 256-half row
            cp16(sbase + B_BYTE_OFF + (slot * BSTG_H + row * LDB_H) * 2 + c * 16,
                 &g_Bh[(size_t)(k0 + row) * D_IN + c * 8]);
        }
        cp_commit();
    };

    // A fragment source: float2 at staging[(wm*32+mi*16 + r)][ks*16 + 2c (+8)]
    const int a_r = lane >> 2;          // 0..7
    const int a_c = 2 * (lane & 3);     // 0,2,4,6
    const uint32_t b_lane_off = ((lane & 15) * LDB_H + (lane >> 4) * 8) * 2;

    auto compute = [&](int slot) {
        const float* stA = smf + slot * ASTG_F;
        const uint32_t bbase = sbase + B_BYTE_OFF + slot * (BSTG_H * 2);
#pragma unroll
        for (int ks = 0; ks < 2; ks++) {
            uint32_t a[2][4], b[4][4];
#pragma unroll
            for (int mi = 0; mi < 2; mi++) {
                const float* p = stA + (wm * 32 + mi * 16 + a_r) * LDA_F + ks * 16 + a_c;
                float2 v0 = *(const float2*)(p);
                float2 v1 = *(const float2*)(p + 8 * LDA_F);
                float2 v2 = *(const float2*)(p + 8);
                float2 v3 = *(const float2*)(p + 8 * LDA_F + 8);
                a[mi][0] = packh2(v0.x, v0.y);
                a[mi][1] = packh2(v1.x, v1.y);
                a[mi][2] = packh2(v2.x, v2.y);
                a[mi][3] = packh2(v3.x, v3.y);
            }
#pragma unroll
            for (int g = 0; g < 4; g++)
                ldsm4t(b[g], bbase + b_lane_off +
                             (ks * 16 * LDB_H + wn * 64 + g * 16) * 2);
#pragma unroll
            for (int mi = 0; mi < 2; mi++)
#pragma unroll
                for (int g = 0; g < 4; g++) {
                    mma_f16(acc[mi][g * 2 + 0], a[mi], b[g][0], b[g][1]);
                    mma_f16(acc[mi][g * 2 + 1], a[mi], b[g][2], b[g][3]);
                }
        }
    };

    // prologue: stages 0..2
    fill(0, 0);
    fill(1, 1);
    fill(2, 2);

    for (int it = 0; it < KT; ++it) {
        cp_wait<2>();
        __syncthreads();
        if (it + 3 < KT) fill((it + 3) & 3, it + 3);
        compute(it & 3);
    }

    // epilogue: relu + store
#pragma unroll
    for (int mi = 0; mi < 2; mi++) {
        int row0 = m0 + wm * 32 + mi * 16 + (lane >> 2);
#pragma unroll
        for (int ni = 0; ni < 8; ni++) {
            int col = wn * 64 + ni * 8 + (lane & 3) * 2;
            if (row0 < N_NODES) {
                float2 v = make_float2(fmaxf(acc[mi][ni][0], 0.f),
                                       fmaxf(acc[mi][ni][1], 0.f));
                *(float2*)&g_h[(size_t)row0 * D_IN + col] = v;
            }
            if (row0 + 8 < N_NODES) {
                float2 v = make_float2(fmaxf(acc[mi][ni][2], 0.f),
                                       fmaxf(acc[mi][ni][3], 0.f));
                *(float2*)&g_h[(size_t)(row0 + 8) * D_IN + col] = v;
            }
        }
    }
}

// ---------------- small dense linears: Y = X @ W -----------------------------
template <int IN, int OUT>
__global__ void k_linear(const float* __restrict__ X,
                         const float* __restrict__ W,
                         float* __restrict__ Y)
{
    int col = threadIdx.x;
    int row = blockIdx.x * blockDim.y + threadIdx.y;
    if (row >= N_NODES) return;
    const float* xr = X + (size_t)row * IN;
    float acc = 0.0f;
#pragma unroll 8
    for (int k = 0; k < IN; k++)
        acc = fmaf(xr[k], W[k * OUT + col], acc);
    Y[(size_t)row * OUT + col] = acc;
}

// ---------------- CSR gather aggregation + bias + relu ------------------------
template <int F>
__global__ void k_gather(const float* __restrict__ X,
                         const float* __restrict__ bias,
                         float* __restrict__ Y)
{
    int f = threadIdx.x;
    int i = blockIdx.x * blockDim.y + threadIdx.y;
    if (i >= N_NODES) return;
    int beg = g_rowptr[i], end = g_rowptr[i + 1];
    float di  = g_dinv[i];
    float acc = X[(size_t)i * F + f] * di;
    int j = beg;
    for (; j + 4 <= end; j += 4) {
        int   s0 = g_csr_src[j],     s1 = g_csr_src[j + 1];
        int   s2 = g_csr_src[j + 2], s3 = g_csr_src[j + 3];
        float w0 = g_csr_w[j],       w1 = g_csr_w[j + 1];
        float w2 = g_csr_w[j + 2],   w3 = g_csr_w[j + 3];
        acc = fmaf(X[(size_t)s0 * F + f], w0, acc);
        acc = fmaf(X[(size_t)s1 * F + f], w1, acc);
        acc = fmaf(X[(size_t)s2 * F + f], w2, acc);
        acc = fmaf(X[(size_t)s3 * F + f], w3, acc);
    }
    for (; j < end; j++)
        acc = fmaf(X[(size_t)g_csr_src[j] * F + f], g_csr_w[j], acc);
    Y[(size_t)i * F + f] = fmaxf(fmaf(acc, di, bias[f]), 0.0f);
}

// ---------------- launch -----------------------------------------------------
extern "C" void kernel_launch(void* const* d_in, const int* in_sizes, int n_in,
                              void* d_out, int out_size)
{
    const float* x    = (const float*)d_in[0];
    const void*  ei   = d_in[1];
    const float* emb  = (const float*)d_in[2];
    const float* W1   = (const float*)d_in[3];
    const float* b1   = (const float*)d_in[4];
    const float* W2   = (const float*)d_in[5];
    const float* b2   = (const float*)d_in[6];
    const float* decW = (const float*)d_in[7];
    float*       out  = (float*)d_out;

    float *gh, *gt1, *ga1, *gt2, *ga2;
    int* gdeg;
    cudaGetSymbolAddress((void**)&gh,  g_h);
    cudaGetSymbolAddress((void**)&gt1, g_t1);
    cudaGetSymbolAddress((void**)&ga1, g_a1);
    cudaGetSymbolAddress((void**)&gt2, g_t2);
    cudaGetSymbolAddress((void**)&ga2, g_a2);
    cudaGetSymbolAddress((void**)&gdeg, g_deg);

    cudaFuncSetAttribute(k_gemm1_f16, cudaFuncAttributeMaxDynamicSharedMemorySize, GEMM_SMEM);

    // graph structure: deg -> scan(+dinv) -> CSR
    cudaMemsetAsync(gdeg, 0, N_NODES * sizeof(int));
    k_detect<<<1, 32>>>(ei);
    k_decode_deg<<<(N_EDGES + 255) / 256, 256>>>(ei);
    k_scan<<<1, 1024>>>();
    k_fill_csr<<<(N_EDGES + 255) / 256, 256>>>();

    // fp16 prep for B only
    k_prep_b<<<(K_PAD * D_IN / 8 + 255) / 256, 256>>>(emb);

    // h = relu(x @ emb) — fp32 A consumed directly
    k_gemm1_f16<<<M_PAD / 128, 512, GEMM_SMEM>>>(x);

    // layer 1: t1 = h @ W1 ; CSR-gather+bias+relu -> a1
    {
        dim3 blk(D_H1, 256 / D_H1);
        k_linear<D_IN, D_H1><<<(N_NODES + blk.y - 1) / blk.y, blk>>>(gh, W1, gt1);
        dim3 gblk(D_H1, 512 / D_H1);
        k_gather<D_H1><<<(N_NODES + gblk.y - 1) / gblk.y, gblk>>>(gt1, b1, ga1);
    }

    // layer 2: t2 = a1 @ W2 ; CSR-gather+bias+relu -> a2
    {
        dim3 blk(D_H2, 256 / D_H2);
        k_linear<D_H1, D_H2><<<(N_NODES + blk.y - 1) / blk.y, blk>>>(ga1, W2, gt2);
        dim3 gblk(D_H2, 512 / D_H2);
        k_gather<D_H2><<<(N_NODES + gblk.y - 1) / gblk.y, gblk>>>(gt2, b2, ga2);
    }

    // decoder: out = a2 @ dec_W
    {
        dim3 blk(D_OUT, 256 / D_OUT);
        k_linear<D_H2, D_OUT><<<(N_NODES + blk.y - 1) / blk.y, blk>>>(ga2, decW, out);
    }
}

// round 15
// speedup vs baseline: 1.0043x; 1.0043x over previous
#include <cuda_runtime.h>
#include <cuda_fp16.h>
#include <math.h>
#include <stdint.h>

#define N_NODES 10000
#define N_EDGES 640000
#define D_IN    256
#define D_H1    64
#define D_H2    32
#define D_OUT   16

#define K_PAD   10016            // 313 * 32
#define M_PAD   10112            // 79 * 128
#define KT      313

// ---------------- scratch (device globals; no allocation allowed) ------------
__device__ __half g_Bh[(size_t)K_PAD * D_IN];    // fp16 emb, K-padded
__device__ float g_h [N_NODES * D_IN];
__device__ float g_t1[N_NODES * D_H1];
__device__ float g_a1[N_NODES * D_H1];
__device__ float g_t2[N_NODES * D_H2];
__device__ float g_a2[N_NODES * D_H2];
__device__ int   g_src[N_EDGES];
__device__ int   g_dst[N_EDGES];
__device__ int   g_csr_src[N_EDGES];
__device__ float g_csr_w[N_EDGES];
__device__ int   g_rowptr[N_NODES + 1];
__device__ int   g_cursor[N_NODES];
__device__ int   g_deg [N_NODES];
__device__ float g_dinv[N_NODES];
__device__ int   g_is64;

// ---------------- edge index dtype detection + decode (+deg count) -----------
__global__ void k_detect(const void* __restrict__ ei) {
    if (threadIdx.x == 0 && blockIdx.x == 0) {
        const long long* p = (const long long*)ei;
        int ok = 1;
        for (int i = 0; i < 16; i++) {
            long long v = p[i];
            if (v < 0 || v >= N_NODES) ok = 0;
        }
        g_is64 = ok;
    }
}

__global__ void k_decode_deg(const void* __restrict__ ei) {
    int e = blockIdx.x * blockDim.x + threadIdx.x;
    if (e >= N_EDGES) return;
    int s, d;
    if (g_is64) {
        const long long* p = (const long long*)ei;
        s = (int)p[e]; d = (int)p[N_EDGES + e];
    } else {
        const int* p = (const int*)ei;
        s = p[e]; d = p[N_EDGES + e];
    }
    g_src[e] = s;
    g_dst[e] = d;
    atomicAdd(&g_deg[d], 1);
}

// ---------------- CSR build: shfl scan + dinv ---------------------------------
__global__ __launch_bounds__(1024) void k_scan() {     // single block
    __shared__ int wsum[32];
    const int t    = threadIdx.x;
    const int lane = t & 31;
    const int wrp  = t >> 5;
    const int base = t * 10;
    int loc[10];
    int s = 0;
#pragma unroll
    for (int j = 0; j < 10; j++) {
        int i = base + j;
        int v = (i < N_NODES) ? g_deg[i] : 0;
        loc[j] = s;
        s += v;
        if (i < N_NODES) g_dinv[i] = rsqrtf((float)(v + 1));
    }
    // warp inclusive scan of s
    int inc = s;
#pragma unroll
    for (int off = 1; off < 32; off <<= 1) {
        int v = __shfl_up_sync(0xffffffffu, inc, off);
        if (lane >= off) inc += v;
    }
    if (lane == 31) wsum[wrp] = inc;
    __syncthreads();
    if (wrp == 0) {
        int v = wsum[lane];
        int wi = v;
#pragma unroll
        for (int off = 1; off < 32; off <<= 1) {
            int u = __shfl_up_sync(0xffffffffu, wi, off);
            if (lane >= off) wi += u;
        }
        wsum[lane] = wi - v;     // exclusive warp prefix
    }
    __syncthreads();
    int pre = wsum[wrp] + inc - s;   // exclusive prefix for this thread
#pragma unroll
    for (int j = 0; j < 10; j++) {
        int i = base + j;
        if (i < N_NODES) {
            g_rowptr[i] = pre + loc[j];
            g_cursor[i] = pre + loc[j];
        }
    }
    if (t == 1023) g_rowptr[N_NODES] = pre + s;
}

__global__ void k_fill_csr() {
    int e = blockIdx.x * blockDim.x + threadIdx.x;
    if (e >= N_EDGES) return;
    int s = g_src[e], d = g_dst[e];
    int pos = atomicAdd(&g_cursor[d], 1);
    g_csr_src[pos] = s;
    g_csr_w[pos]   = g_dinv[s];
}

// ---------------- fp16 prep for B (emb) ---------------------------------------
__global__ void k_prep_b(const float* __restrict__ emb) {
    int chunk = blockIdx.x * blockDim.x + threadIdx.x; // 8-half chunk
    if (chunk >= K_PAD * D_IN / 8) return;
    int row = chunk >> 5;
    int c   = chunk & 31;
    __half2 h[4];
    if (row < N_NODES) {
        const float4* p = (const float4*)&emb[(size_t)row * D_IN + c * 8];
        float4 v0 = p[0], v1 = p[1];
        h[0] = __floats2half2_rn(v0.x, v0.y);
        h[1] = __floats2half2_rn(v0.z, v0.w);
        h[2] = __floats2half2_rn(v1.x, v1.y);
        h[3] = __floats2half2_rn(v1.z, v1.w);
    } else {
        h[0] = h[1] = h[2] = h[3] = __floats2half2_rn(0.f, 0.f);
    }
    *(uint4*)&g_Bh[(size_t)row * D_IN + c * 8] = *(uint4*)h;
}

// ---------------- GEMM1 (fp16 HMMA, fp32 A staged + inline convert) -----------
// BM=128 BN=256 BK=32, 512 threads (16 warps = 4M x 4N), 4 smem stages.
// A staged as fp32 (cp.async, zero-fill tails); fragments built by LDS.64+cvt.
#define LDA_F 40                       // fp32 A stage stride (floats) — conflict-free
#define LDB_H 264
#define ASTG_F (128 * LDA_F)           // 5120 floats = 20480 B per stage
#define BSTG_H (32 * LDB_H)            // 8448 halfs  = 16896 B per stage
#define B_BYTE_OFF (4 * ASTG_F * 4)    // 81920
#define GEMM_SMEM (4 * ASTG_F * 4 + 4 * BSTG_H * 2)   // 149504 B

__device__ __forceinline__ uint32_t smem_u32(const void* p) {
    uint32_t a;
    asm("{ .reg .u64 t; cvta.to.shared.u64 t, %1; cvt.u32.u64 %0, t; }"
        : "=r"(a) : "l"(p));
    return a;
}
__device__ __forceinline__ void cp16(uint32_t dst, const void* src) {
    asm volatile("cp.async.cg.shared.global [%0], [%1], 16;" :: "r"(dst), "l"(src) : "memory");
}
__device__ __forceinline__ void cp16p(uint32_t dst, const void* src, bool valid) {
    int sz = valid ? 16 : 0;
    asm volatile("cp.async.cg.shared.global [%0], [%1], 16, %2;"
                 :: "r"(dst), "l"(src), "r"(sz) : "memory");
}
__device__ __forceinline__ void cp_commit() {
    asm volatile("cp.async.commit_group;" ::: "memory");
}
template <int NW>
__device__ __forceinline__ void cp_wait() {
    asm volatile("cp.async.wait_group %0;" :: "n"(NW) : "memory");
}
__device__ __forceinline__ void ldsm4t(uint32_t* r, uint32_t addr) {
    asm volatile("ldmatrix.sync.aligned.m8n8.x4.trans.shared.b16 {%0,%1,%2,%3}, [%4];"
                 : "=r"(r[0]), "=r"(r[1]), "=r"(r[2]), "=r"(r[3]) : "r"(addr));
}
__device__ __forceinline__ void mma_f16(float* c, const uint32_t* a, uint32_t b0, uint32_t b1) {
    asm volatile(
        "mma.sync.aligned.m16n8k16.row.col.f32.f16.f16.f32 "
        "{%0,%1,%2,%3}, {%4,%5,%6,%7}, {%8,%9}, {%0,%1,%2,%3};"
        : "+f"(c[0]), "+f"(c[1]), "+f"(c[2]), "+f"(c[3])
        : "r"(a[0]), "r"(a[1]), "r"(a[2]), "r"(a[3]), "r"(b0), "r"(b1));
}
__device__ __forceinline__ uint32_t packh2(float lo, float hi) {
    uint32_t r;
    asm("cvt.rn.f16x2.f32 %0, %1, %2;" : "=r"(r) : "f"(hi), "f"(lo));
    return r;
}

__global__ __launch_bounds__(512, 1)
void k_gemm1_f16(const float* __restrict__ X)   // x [10000,10000] fp32
{
    extern __shared__ float smf[];

    const int tid  = threadIdx.x;
    const int lane = tid & 31;
    const int wid  = tid >> 5;
    const int wm   = wid & 3;        // 0..3 (M)
    const int wn   = wid >> 2;       // 0..3 (N)
    const int m0   = blockIdx.x * 128;
    const uint32_t sbase = smem_u32(smf);

    float acc[2][8][4];
#pragma unroll
    for (int mi = 0; mi < 2; mi++)
#pragma unroll
        for (int ni = 0; ni < 8; ni++)
#pragma unroll
            for (int r = 0; r < 4; r++) acc[mi][ni][r] = 0.0f;

    // fill: A 1024 fp32 chunks (2/thread), B 1024 fp16 chunks (2/thread)
    auto fill = [&](int slot, int it) {
        const int k0 = it * 32;
#pragma unroll
        for (int i = 0; i < 2; i++) {
            int ch  = tid + i * 512;
            int row = ch >> 3, c4 = ch & 7;          // 8 chunks per 32-float row
            int gm  = m0 + row;
            int gk  = k0 + c4 * 4;
            bool v  = (gm < N_NODES) && (gk < N_NODES);
            const float* src = v ? &X[(size_t)gm * N_NODES + gk] : X;
            cp16p(sbase + (slot * ASTG_F + row * LDA_F + c4 * 4) * 4, src, v);
        }
#pragma unroll
        for (int i = 0; i < 2; i++) {
            int ch  = tid + i * 512;
            int row = ch >> 5, c = ch & 31;          // 32 chunks per 256-half row
            cp16(sbase + B_BYTE_OFF + (slot * BSTG_H + row * LDB_H) * 2 + c * 16,
                 &g_Bh[(size_t)(k0 + row) * D_IN + c * 8]);
        }
        cp_commit();
    };

    // A fragment source: float2 at staging[(wm*32+mi*16 + r)][ks*16 + 2c (+8)]
    const int a_r = lane >> 2;          // 0..7
    const int a_c = 2 * (lane & 3);     // 0,2,4,6
    const uint32_t b_lane_off = ((lane & 15) * LDB_H + (lane >> 4) * 8) * 2;

    auto compute = [&](int slot) {
        const float* stA = smf + slot * ASTG_F;
        const uint32_t bbase = sbase + B_BYTE_OFF + slot * (BSTG_H * 2);
#pragma unroll
        for (int ks = 0; ks < 2; ks++) {
            uint32_t a[2][4], b[4][4];
#pragma unroll
            for (int mi = 0; mi < 2; mi++) {
                const float* p = stA + (wm * 32 + mi * 16 + a_r) * LDA_F + ks * 16 + a_c;
                float2 v0 = *(const float2*)(p);
                float2 v1 = *(const float2*)(p + 8 * LDA_F);
                float2 v2 = *(const float2*)(p + 8);
                float2 v3 = *(const float2*)(p + 8 * LDA_F + 8);
                a[mi][0] = packh2(v0.x, v0.y);
                a[mi][1] = packh2(v1.x, v1.y);
                a[mi][2] = packh2(v2.x, v2.y);
                a[mi][3] = packh2(v3.x, v3.y);
            }
#pragma unroll
            for (int g = 0; g < 4; g++)
                ldsm4t(b[g], bbase + b_lane_off +
                             (ks * 16 * LDB_H + wn * 64 + g * 16) * 2);
#pragma unroll
            for (int mi = 0; mi < 2; mi++)
#pragma unroll
                for (int g = 0; g < 4; g++) {
                    mma_f16(acc[mi][g * 2 + 0], a[mi], b[g][0], b[g][1]);
                    mma_f16(acc[mi][g * 2 + 1], a[mi], b[g][2], b[g][3]);
                }
        }
    };

    // prologue: stages 0..2
    fill(0, 0);
    fill(1, 1);
    fill(2, 2);

    for (int it = 0; it < KT; ++it) {
        cp_wait<2>();
        __syncthreads();
        if (it + 3 < KT) fill((it + 3) & 3, it + 3);
        compute(it & 3);
    }

    // epilogue: relu + store
#pragma unroll
    for (int mi = 0; mi < 2; mi++) {
        int row0 = m0 + wm * 32 + mi * 16 + (lane >> 2);
#pragma unroll
        for (int ni = 0; ni < 8; ni++) {
            int col = wn * 64 + ni * 8 + (lane & 3) * 2;
            if (row0 < N_NODES) {
                float2 v = make_float2(fmaxf(acc[mi][ni][0], 0.f),
                                       fmaxf(acc[mi][ni][1], 0.f));
                *(float2*)&g_h[(size_t)row0 * D_IN + col] = v;
            }
            if (row0 + 8 < N_NODES) {
                float2 v = make_float2(fmaxf(acc[mi][ni][2], 0.f),
                                       fmaxf(acc[mi][ni][3], 0.f));
                *(float2*)&g_h[(size_t)(row0 + 8) * D_IN + col] = v;
            }
        }
    }
}

// ---------------- small dense linears: Y = X @ W -----------------------------
template <int IN, int OUT>
__global__ void k_linear(const float* __restrict__ X,
                         const float* __restrict__ W,
                         float* __restrict__ Y)
{
    int col = threadIdx.x;
    int row = blockIdx.x * blockDim.y + threadIdx.y;
    if (row >= N_NODES) return;
    const float* xr = X + (size_t)row * IN;
    float acc = 0.0f;
#pragma unroll 8
    for (int k = 0; k < IN; k++)
        acc = fmaf(xr[k], W[k * OUT + col], acc);
    Y[(size_t)row * OUT + col] = acc;
}

// ---------------- CSR gather aggregation + bias + relu ------------------------
template <int F>
__global__ void k_gather(const float* __restrict__ X,
                         const float* __restrict__ bias,
                         float* __restrict__ Y)
{
    int f = threadIdx.x;
    int i = blockIdx.x * blockDim.y + threadIdx.y;
    if (i >= N_NODES) return;
    int beg = g_rowptr[i], end = g_rowptr[i + 1];
    float di  = g_dinv[i];
    float acc = X[(size_t)i * F + f] * di;
    int j = beg;
    for (; j + 4 <= end; j += 4) {
        int   s0 = g_csr_src[j],     s1 = g_csr_src[j + 1];
        int   s2 = g_csr_src[j + 2], s3 = g_csr_src[j + 3];
        float w0 = g_csr_w[j],       w1 = g_csr_w[j + 1];
        float w2 = g_csr_w[j + 2],   w3 = g_csr_w[j + 3];
        acc = fmaf(X[(size_t)s0 * F + f], w0, acc);
        acc = fmaf(X[(size_t)s1 * F + f], w1, acc);
        acc = fmaf(X[(size_t)s2 * F + f], w2, acc);
        acc = fmaf(X[(size_t)s3 * F + f], w3, acc);
    }
    for (; j < end; j++)
        acc = fmaf(X[(size_t)g_csr_src[j] * F + f], g_csr_w[j], acc);
    Y[(size_t)i * F + f] = fmaxf(fmaf(acc, di, bias[f]), 0.0f);
}

// ---------------- launch -----------------------------------------------------
extern "C" void kernel_launch(void* const* d_in, const int* in_sizes, int n_in,
                              void* d_out, int out_size)
{
    const float* x    = (const float*)d_in[0];
    const void*  ei   = d_in[1];
    const float* emb  = (const float*)d_in[2];
    const float* W1   = (const float*)d_in[3];
    const float* b1   = (const float*)d_in[4];
    const float* W2   = (const float*)d_in[5];
    const float* b2   = (const float*)d_in[6];
    const float* decW = (const float*)d_in[7];
    float*       out  = (float*)d_out;

    float *gh, *gt1, *ga1, *gt2, *ga2;
    int* gdeg;
    cudaGetSymbolAddress((void**)&gh,  g_h);
    cudaGetSymbolAddress((void**)&gt1, g_t1);
    cudaGetSymbolAddress((void**)&ga1, g_a1);
    cudaGetSymbolAddress((void**)&gt2, g_t2);
    cudaGetSymbolAddress((void**)&ga2, g_a2);
    cudaGetSymbolAddress((void**)&gdeg, g_deg);

    cudaFuncSetAttribute(k_gemm1_f16, cudaFuncAttributeMaxDynamicSharedMemorySize, GEMM_SMEM);

    // graph structure: deg -> scan(+dinv) -> CSR
    cudaMemsetAsync(gdeg, 0, N_NODES * sizeof(int));
    k_detect<<<1, 32>>>(ei);
    k_decode_deg<<<(N_EDGES + 255) / 256, 256>>>(ei);
    k_scan<<<1, 1024>>>();
    k_fill_csr<<<(N_EDGES + 255) / 256, 256>>>();

    // fp16 prep for B only
    k_prep_b<<<(K_PAD * D_IN / 8 + 255) / 256, 256>>>(emb);

    // h = relu(x @ emb) — fp32 A consumed directly
    k_gemm1_f16<<<M_PAD / 128, 512, GEMM_SMEM>>>(x);

    // layer 1: t1 = h @ W1 ; CSR-gather+bias+relu -> a1
    {
        dim3 blk(D_H1, 256 / D_H1);
        k_linear<D_IN, D_H1><<<(N_NODES + blk.y - 1) / blk.y, blk>>>(gh, W1, gt1);
        dim3 gblk(D_H1, 512 / D_H1);
        k_gather<D_H1><<<(N_NODES + gblk.y - 1) / gblk.y, gblk>>>(gt1, b1, ga1);
    }

    // layer 2: t2 = a1 @ W2 ; CSR-gather+bias+relu -> a2
    {
        dim3 blk(D_H2, 256 / D_H2);
        k_linear<D_H1, D_H2><<<(N_NODES + blk.y - 1) / blk.y, blk>>>(ga1, W2, gt2);
        dim3 gblk(D_H2, 512 / D_H2);
        k_gather<D_H2><<<(N_NODES + gblk.y - 1) / gblk.y, gblk>>>(gt2, b2, ga2);
    }

    // decoder: out = a2 @ dec_W
    {
        dim3 blk(D_OUT, 256 / D_OUT);
        k_linear<D_H2, D_OUT><<<(N_NODES + blk.y - 1) / blk.y, blk>>>(ga2, decW, out);
    }
}

// round 16
// speedup vs baseline: 1.0048x; 1.0005x over previous
#include <cuda_runtime.h>
#include <cuda_fp16.h>
#include <math.h>
#include <stdint.h>

#define N_NODES 10000
#define N_EDGES 640000
#define D_IN    256
#define D_H1    64
#define D_H2    32
#define D_OUT   16

#define K_PAD   10016            // 313 * 32
#define M_PAD   10112            // 79 * 128
#define KT      313

// ---------------- scratch (device globals; no allocation allowed) ------------
__device__ __half g_Bh[(size_t)K_PAD * D_IN];    // fp16 emb, K-padded
__device__ float g_h [N_NODES * D_IN];
__device__ float g_t1[N_NODES * D_H1];
__device__ float g_a1[N_NODES * D_H1];
__device__ float g_t2[N_NODES * D_H2];
__device__ float g_a2[N_NODES * D_H2];
__device__ int   g_src[N_EDGES];
__device__ int   g_dst[N_EDGES];
__device__ int   g_csr_src[N_EDGES];
__device__ float g_csr_w[N_EDGES];
__device__ int   g_rowptr[N_NODES + 1];
__device__ int   g_cursor[N_NODES];
__device__ int   g_deg [N_NODES];
__device__ float g_dinv[N_NODES];
__device__ int   g_is64;

// ---------------- edge index dtype detection + decode (+deg count) -----------
__global__ void k_detect(const void* __restrict__ ei) {
    if (threadIdx.x == 0 && blockIdx.x == 0) {
        const long long* p = (const long long*)ei;
        int ok = 1;
        for (int i = 0; i < 16; i++) {
            long long v = p[i];
            if (v < 0 || v >= N_NODES) ok = 0;
        }
        g_is64 = ok;
    }
}

__global__ void k_decode_deg(const void* __restrict__ ei) {
    int e = blockIdx.x * blockDim.x + threadIdx.x;
    if (e >= N_EDGES) return;
    int s, d;
    if (g_is64) {
        const long long* p = (const long long*)ei;
        s = (int)p[e]; d = (int)p[N_EDGES + e];
    } else {
        const int* p = (const int*)ei;
        s = p[e]; d = p[N_EDGES + e];
    }
    g_src[e] = s;
    g_dst[e] = d;
    atomicAdd(&g_deg[d], 1);
}

// ---------------- CSR build: shfl scan + dinv ---------------------------------
__global__ __launch_bounds__(1024) void k_scan() {     // single block
    __shared__ int wsum[32];
    const int t    = threadIdx.x;
    const int lane = t & 31;
    const int wrp  = t >> 5;
    const int base = t * 10;
    int loc[10];
    int s = 0;
#pragma unroll
    for (int j = 0; j < 10; j++) {
        int i = base + j;
        int v = (i < N_NODES) ? g_deg[i] : 0;
        loc[j] = s;
        s += v;
        if (i < N_NODES) g_dinv[i] = rsqrtf((float)(v + 1));
    }
    // warp inclusive scan of s
    int inc = s;
#pragma unroll
    for (int off = 1; off < 32; off <<= 1) {
        int v = __shfl_up_sync(0xffffffffu, inc, off);
        if (lane >= off) inc += v;
    }
    if (lane == 31) wsum[wrp] = inc;
    __syncthreads();
    if (wrp == 0) {
        int v = wsum[lane];
        int wi = v;
#pragma unroll
        for (int off = 1; off < 32; off <<= 1) {
            int u = __shfl_up_sync(0xffffffffu, wi, off);
            if (lane >= off) wi += u;
        }
        wsum[lane] = wi - v;     // exclusive warp prefix
    }
    __syncthreads();
    int pre = wsum[wrp] + inc - s;   // exclusive prefix for this thread
#pragma unroll
    for (int j = 0; j < 10; j++) {
        int i = base + j;
        if (i < N_NODES) {
            g_rowptr[i] = pre + loc[j];
            g_cursor[i] = pre + loc[j];
        }
    }
    if (t == 1023) g_rowptr[N_NODES] = pre + s;
}

__global__ void k_fill_csr() {
    int e = blockIdx.x * blockDim.x + threadIdx.x;
    if (e >= N_EDGES) return;
    int s = g_src[e], d = g_dst[e];
    int pos = atomicAdd(&g_cursor[d], 1);
    g_csr_src[pos] = s;
    g_csr_w[pos]   = g_dinv[s];
}

// ---------------- fp16 prep for B (emb) ---------------------------------------
__global__ void k_prep_b(const float* __restrict__ emb) {
    int chunk = blockIdx.x * blockDim.x + threadIdx.x; // 8-half chunk
    if (chunk >= K_PAD * D_IN / 8) return;
    int row = chunk >> 5;
    int c   = chunk & 31;
    __half2 h[4];
    if (row < N_NODES) {
        const float4* p = (const float4*)&emb[(size_t)row * D_IN + c * 8];
        float4 v0 = p[0], v1 = p[1];
        h[0] = __floats2half2_rn(v0.x, v0.y);
        h[1] = __floats2half2_rn(v0.z, v0.w);
        h[2] = __floats2half2_rn(v1.x, v1.y);
        h[3] = __floats2half2_rn(v1.z, v1.w);
    } else {
        h[0] = h[1] = h[2] = h[3] = __floats2half2_rn(0.f, 0.f);
    }
    *(uint4*)&g_Bh[(size_t)row * D_IN + c * 8] = *(uint4*)h;
}

// ---------------- GEMM1 (fp16 HMMA, fp32 A staged + inline convert) -----------
// BM=128 BN=256 BK=32, 512 threads (16 warps = 4M x 4N), 4 smem stages.
// A staged as fp32 (cp.async, zero-fill tails); fragments built by LDS.64+cvt.
#define LDA_F 40                       // fp32 A stage stride (floats) — conflict-free
#define LDB_H 264
#define ASTG_F (128 * LDA_F)           // 5120 floats = 20480 B per stage
#define BSTG_H (32 * LDB_H)            // 8448 halfs  = 16896 B per stage
#define B_BYTE_OFF (4 * ASTG_F * 4)    // 81920
#define GEMM_SMEM (4 * ASTG_F * 4 + 4 * BSTG_H * 2)   // 149504 B

__device__ __forceinline__ uint32_t smem_u32(const void* p) {
    uint32_t a;
    asm("{ .reg .u64 t; cvta.to.shared.u64 t, %1; cvt.u32.u64 %0, t; }"
        : "=r"(a) : "l"(p));
    return a;
}
__device__ __forceinline__ void cp16(uint32_t dst, const void* src) {
    asm volatile("cp.async.cg.shared.global [%0], [%1], 16;" :: "r"(dst), "l"(src) : "memory");
}
__device__ __forceinline__ void cp16p(uint32_t dst, const void* src, bool valid) {
    int sz = valid ? 16 : 0;
    asm volatile("cp.async.cg.shared.global [%0], [%1], 16, %2;"
                 :: "r"(dst), "l"(src), "r"(sz) : "memory");
}
__device__ __forceinline__ void cp_commit() {
    asm volatile("cp.async.commit_group;" ::: "memory");
}
template <int NW>
__device__ __forceinline__ void cp_wait() {
    asm volatile("cp.async.wait_group %0;" :: "n"(NW) : "memory");
}
__device__ __forceinline__ void ldsm4t(uint32_t* r, uint32_t addr) {
    asm volatile("ldmatrix.sync.aligned.m8n8.x4.trans.shared.b16 {%0,%1,%2,%3}, [%4];"
                 : "=r"(r[0]), "=r"(r[1]), "=r"(r[2]), "=r"(r[3]) : "r"(addr));
}
__device__ __forceinline__ void mma_f16(float* c, const uint32_t* a, uint32_t b0, uint32_t b1) {
    asm volatile(
        "mma.sync.aligned.m16n8k16.row.col.f32.f16.f16.f32 "
        "{%0,%1,%2,%3}, {%4,%5,%6,%7}, {%8,%9}, {%0,%1,%2,%3};"
        : "+f"(c[0]), "+f"(c[1]), "+f"(c[2]), "+f"(c[3])
        : "r"(a[0]), "r"(a[1]), "r"(a[2]), "r"(a[3]), "r"(b0), "r"(b1));
}
__device__ __forceinline__ uint32_t packh2(float lo, float hi) {
    uint32_t r;
    asm("cvt.rn.f16x2.f32 %0, %1, %2;" : "=r"(r) : "f"(hi), "f"(lo));
    return r;
}

__global__ __launch_bounds__(512, 1)
void k_gemm1_f16(const float* __restrict__ X)   // x [10000,10000] fp32
{
    extern __shared__ float smf[];

    const int tid  = threadIdx.x;
    const int lane = tid & 31;
    const int wid  = tid >> 5;
    const int wm   = wid & 3;        // 0..3 (M)
    const int wn   = wid >> 2;       // 0..3 (N)
    const int m0   = blockIdx.x * 128;
    const uint32_t sbase = smem_u32(smf);

    float acc[2][8][4];
#pragma unroll
    for (int mi = 0; mi < 2; mi++)
#pragma unroll
        for (int ni = 0; ni < 8; ni++)
#pragma unroll
            for (int r = 0; r < 4; r++) acc[mi][ni][r] = 0.0f;

    // fill: A 1024 fp32 chunks (2/thread), B 1024 fp16 chunks (2/thread)
    auto fill = [&](int slot, int it) {
        const int k0 = it * 32;
#pragma unroll
        for (int i = 0; i < 2; i++) {
            int ch  = tid + i * 512;
            int row = ch >> 3, c4 = ch & 7;          // 8 chunks per 32-float row
            int gm  = m0 + row;
            int gk  = k0 + c4 * 4;
            bool v  = (gm < N_NODES) && (gk < N_NODES);
            const float* src = v ? &X[(size_t)gm * N_NODES + gk] : X;
            cp16p(sbase + (slot * ASTG_F + row * LDA_F + c4 * 4) * 4, src, v);
        }
#pragma unroll
        for (int i = 0; i < 2; i++) {
            int ch  = tid + i * 512;
            int row = ch >> 5, c = ch & 31;          // 32 chunks per 256-half row
            cp16(sbase + B_BYTE_OFF + (slot * BSTG_H + row * LDB_H) * 2 + c * 16,
                 &g_Bh[(size_t)(k0 + row) * D_IN + c * 8]);
        }
        cp_commit();
    };

    // A fragment source: float2 at staging[(wm*32+mi*16 + r)][ks*16 + 2c (+8)]
    const int a_r = lane >> 2;          // 0..7
    const int a_c = 2 * (lane & 3);     // 0,2,4,6
    const uint32_t b_lane_off = ((lane & 15) * LDB_H + (lane >> 4) * 8) * 2;

    auto compute = [&](int slot) {
        const float* stA = smf + slot * ASTG_F;
        const uint32_t bbase = sbase + B_BYTE_OFF + slot * (BSTG_H * 2);
#pragma unroll
        for (int ks = 0; ks < 2; ks++) {
            uint32_t a[2][4], b[4][4];
#pragma unroll
            for (int mi = 0; mi < 2; mi++) {
                const float* p = stA + (wm * 32 + mi * 16 + a_r) * LDA_F + ks * 16 + a_c;
                float2 v0 = *(const float2*)(p);
                float2 v1 = *(const float2*)(p + 8 * LDA_F);
                float2 v2 = *(const float2*)(p + 8);
                float2 v3 = *(const float2*)(p + 8 * LDA_F + 8);
                a[mi][0] = packh2(v0.x, v0.y);
                a[mi][1] = packh2(v1.x, v1.y);
                a[mi][2] = packh2(v2.x, v2.y);
                a[mi][3] = packh2(v3.x, v3.y);
            }
#pragma unroll
            for (int g = 0; g < 4; g++)
                ldsm4t(b[g], bbase + b_lane_off +
                             (ks * 16 * LDB_H + wn * 64 + g * 16) * 2);
#pragma unroll
            for (int mi = 0; mi < 2; mi++)
#pragma unroll
                for (int g = 0; g < 4; g++) {
                    mma_f16(acc[mi][g * 2 + 0], a[mi], b[g][0], b[g][1]);
                    mma_f16(acc[mi][g * 2 + 1], a[mi], b[g][2], b[g][3]);
                }
        }
    };

    // prologue: stages 0..2
    fill(0, 0);
    fill(1, 1);
    fill(2, 2);

    for (int it = 0; it < KT; ++it) {
        cp_wait<2>();
        __syncthreads();
        if (it + 3 < KT) fill((it + 3) & 3, it + 3);
        compute(it & 3);
    }

    // epilogue: relu + store
#pragma unroll
    for (int mi = 0; mi < 2; mi++) {
        int row0 = m0 + wm * 32 + mi * 16 + (lane >> 2);
#pragma unroll
        for (int ni = 0; ni < 8; ni++) {
            int col = wn * 64 + ni * 8 + (lane & 3) * 2;
            if (row0 < N_NODES) {
                float2 v = make_float2(fmaxf(acc[mi][ni][0], 0.f),
                                       fmaxf(acc[mi][ni][1], 0.f));
                *(float2*)&g_h[(size_t)row0 * D_IN + col] = v;
            }
            if (row0 + 8 < N_NODES) {
                float2 v = make_float2(fmaxf(acc[mi][ni][2], 0.f),
                                       fmaxf(acc[mi][ni][3], 0.f));
                *(float2*)&g_h[(size_t)(row0 + 8) * D_IN + col] = v;
            }
        }
    }
}

// ---------------- small dense linears: Y = X @ W -----------------------------
template <int IN, int OUT>
__global__ void k_linear(const float* __restrict__ X,
                         const float* __restrict__ W,
                         float* __restrict__ Y)
{
    int col = threadIdx.x;
    int row = blockIdx.x * blockDim.y + threadIdx.y;
    if (row >= N_NODES) return;
    const float* xr = X + (size_t)row * IN;
    float acc = 0.0f;
#pragma unroll 8
    for (int k = 0; k < IN; k++)
        acc = fmaf(xr[k], W[k * OUT + col], acc);
    Y[(size_t)row * OUT + col] = acc;
}

// ---------------- CSR gather aggregation + bias + relu ------------------------
template <int F>
__global__ void k_gather(const float* __restrict__ X,
                         const float* __restrict__ bias,
                         float* __restrict__ Y)
{
    int f = threadIdx.x;
    int i = blockIdx.x * blockDim.y + threadIdx.y;
    if (i >= N_NODES) return;
    int beg = g_rowptr[i], end = g_rowptr[i + 1];
    float di  = g_dinv[i];
    float acc = X[(size_t)i * F + f] * di;
    int j = beg;
    for (; j + 4 <= end; j += 4) {
        int   s0 = g_csr_src[j],     s1 = g_csr_src[j + 1];
        int   s2 = g_csr_src[j + 2], s3 = g_csr_src[j + 3];
        float w0 = g_csr_w[j],       w1 = g_csr_w[j + 1];
        float w2 = g_csr_w[j + 2],   w3 = g_csr_w[j + 3];
        acc = fmaf(X[(size_t)s0 * F + f], w0, acc);
        acc = fmaf(X[(size_t)s1 * F + f], w1, acc);
        acc = fmaf(X[(size_t)s2 * F + f], w2, acc);
        acc = fmaf(X[(size_t)s3 * F + f], w3, acc);
    }
    for (; j < end; j++)
        acc = fmaf(X[(size_t)g_csr_src[j] * F + f], g_csr_w[j], acc);
    Y[(size_t)i * F + f] = fmaxf(fmaf(acc, di, bias[f]), 0.0f);
}

// ---------------- launch -----------------------------------------------------
extern "C" void kernel_launch(void* const* d_in, const int* in_sizes, int n_in,
                              void* d_out, int out_size)
{
    const float* x    = (const float*)d_in[0];
    const void*  ei   = d_in[1];
    const float* emb  = (const float*)d_in[2];
    const float* W1   = (const float*)d_in[3];
    const float* b1   = (const float*)d_in[4];
    const float* W2   = (const float*)d_in[5];
    const float* b2   = (const float*)d_in[6];
    const float* decW = (const float*)d_in[7];
    float*       out  = (float*)d_out;

    float *gh, *gt1, *ga1, *gt2, *ga2;
    int* gdeg;
    cudaGetSymbolAddress((void**)&gh,  g_h);
    cudaGetSymbolAddress((void**)&gt1, g_t1);
    cudaGetSymbolAddress((void**)&ga1, g_a1);
    cudaGetSymbolAddress((void**)&gt2, g_t2);
    cudaGetSymbolAddress((void**)&ga2, g_a2);
    cudaGetSymbolAddress((void**)&gdeg, g_deg);

    cudaFuncSetAttribute(k_gemm1_f16, cudaFuncAttributeMaxDynamicSharedMemorySize, GEMM_SMEM);

    // graph structure: deg -> scan(+dinv) -> CSR
    cudaMemsetAsync(gdeg, 0, N_NODES * sizeof(int));
    k_detect<<<1, 32>>>(ei);
    k_decode_deg<<<(N_EDGES + 255) / 256, 256>>>(ei);
    k_scan<<<1, 1024>>>();
    k_fill_csr<<<(N_EDGES + 255) / 256, 256>>>();

    // fp16 prep for B only
    k_prep_b<<<(K_PAD * D_IN / 8 + 255) / 256, 256>>>(emb);

    // h = relu(x @ emb) — fp32 A consumed directly
    k_gemm1_f16<<<M_PAD / 128, 512, GEMM_SMEM>>>(x);

    // layer 1: t1 = h @ W1 ; CSR-gather+bias+relu -> a1
    {
        dim3 blk(D_H1, 256 / D_H1);
        k_linear<D_IN, D_H1><<<(N_NODES + blk.y - 1) / blk.y, blk>>>(gh, W1, gt1);
        dim3 gblk(D_H1, 512 / D_H1);
        k_gather<D_H1><<<(N_NODES + gblk.y - 1) / gblk.y, gblk>>>(gt1, b1, ga1);
    }

    // layer 2: t2 = a1 @ W2 ; CSR-gather+bias+relu -> a2
    {
        dim3 blk(D_H2, 256 / D_H2);
        k_linear<D_H1, D_H2><<<(N_NODES + blk.y - 1) / blk.y, blk>>>(ga1, W2, gt2);
        dim3 gblk(D_H2, 512 / D_H2);
        k_gather<D_H2><<<(N_NODES + gblk.y - 1) / gblk.y, gblk>>>(gt2, b2, ga2);
    }

    // decoder: out = a2 @ dec_W
    {
        dim3 blk(D_OUT, 256 / D_OUT);
        k_linear<D_H2, D_OUT><<<(N_NODES + blk.y - 1) / blk.y, blk>>>(ga2, decW, out);
    }
}